// round 2
// baseline (speedup 1.0000x reference)
#include <cuda_runtime.h>

#define DIM 300
#define C 16
#define NPTS 1048576   // 2^20
#define PLANE (DIM * DIM)

// Scratch: planes transposed to (H, W, C); lines transposed to (pos, C).
// Index 0 -> data for out_x (plane_yz, line_x)
// Index 1 -> data for out_y (plane_xz, line_y)
// Index 2 -> data for out_z (plane_xy, line_z)
__device__ float g_plane_t[3][PLANE * C];
__device__ float g_line_t[3][DIM * C];

__global__ void transpose_kernel(const float* __restrict__ pxy,
                                 const float* __restrict__ pyz,
                                 const float* __restrict__ pxz,
                                 const float* __restrict__ lx,
                                 const float* __restrict__ ly,
                                 const float* __restrict__ lz) {
    int id = blockIdx.x * blockDim.x + threadIdx.x;
    if (id < 3 * PLANE) {
        int p = id / PLANE;        // uniform-ish per block region
        int pos = id - p * PLANE;  // (y*W + x), consecutive threads -> consecutive x
        const float* src = (p == 0) ? pyz : (p == 1) ? pxz : pxy;
        float v[C];
#pragma unroll
        for (int c = 0; c < C; c++) v[c] = __ldg(&src[c * PLANE + pos]);
        float4* dst = reinterpret_cast<float4*>(&g_plane_t[p][pos * C]);
#pragma unroll
        for (int j = 0; j < 4; j++)
            dst[j] = make_float4(v[4 * j], v[4 * j + 1], v[4 * j + 2], v[4 * j + 3]);
    } else if (id < 3 * PLANE + 3 * DIM) {
        int r = id - 3 * PLANE;
        int p = r / DIM;
        int pos = r - p * DIM;
        const float* src = (p == 0) ? lx : (p == 1) ? ly : lz;
        float v[C];
#pragma unroll
        for (int c = 0; c < C; c++) v[c] = __ldg(&src[c * DIM + pos]);
        float4* dst = reinterpret_cast<float4*>(&g_line_t[p][pos * C]);
#pragma unroll
        for (int j = 0; j < 4; j++)
            dst[j] = make_float4(v[4 * j], v[4 * j + 1], v[4 * j + 2], v[4 * j + 3]);
    }
}

__device__ __forceinline__ float4 f4_fma(float4 a, float s, float4 acc) {
    acc.x = fmaf(a.x, s, acc.x);
    acc.y = fmaf(a.y, s, acc.y);
    acc.z = fmaf(a.z, s, acc.z);
    acc.w = fmaf(a.w, s, acc.w);
    return acc;
}

// One thread = one (output o, point n, channel-quarter q). 4 threads/point.
// idx layout: q fastest, then n, then o -> float4 output writes are fully coalesced:
// out float4 index == idx.
__global__ void __launch_bounds__(256) sample_kernel(
    const float* __restrict__ coords_plane,   // (3, N, 2)
    const float* __restrict__ coords_line,    // (3, N, 2)
    float* __restrict__ out)                  // (3, N, 16)
{
    int idx = blockIdx.x * blockDim.x + threadIdx.x;   // < 3 * N * 4 = 12,582,912
    int q = idx & 3;
    int t = idx >> 2;           // (o, n) packed; t < 3*N
    int o = t >> 20;            // N = 2^20
    int n = t & (NPTS - 1);

    // out_x uses coords_plane[1]; out_y uses [2]; out_z uses [0]
    int po = (o == 0) ? 1 : (o == 1) ? 2 : 0;

    float2 pc = __ldg(&reinterpret_cast<const float2*>(coords_plane)[po * NPTS + n]);
    float2 lc = __ldg(&reinterpret_cast<const float2*>(coords_line)[o * NPTS + n]);

    // ---- plane bilinear ----
    const float S = 0.5f * (DIM - 1);
    float ix = (pc.x + 1.0f) * S;
    float iy = (pc.y + 1.0f) * S;
    float fx = floorf(ix), fy = floorf(iy);
    float wx = ix - fx, wy = iy - fy;
    int x0 = min(max(__float2int_rn(fx), 0), DIM - 1);
    int x1 = min(x0 + 1, DIM - 1);
    int y0 = min(max(__float2int_rn(fy), 0), DIM - 1);
    int y1 = min(y0 + 1, DIM - 1);

    const float* P = g_plane_t[o];
    int co = q * 4;
    float4 v00 = *reinterpret_cast<const float4*>(&P[(y0 * DIM + x0) * C + co]);
    float4 v01 = *reinterpret_cast<const float4*>(&P[(y0 * DIM + x1) * C + co]);
    float4 v10 = *reinterpret_cast<const float4*>(&P[(y1 * DIM + x0) * C + co]);
    float4 v11 = *reinterpret_cast<const float4*>(&P[(y1 * DIM + x1) * C + co]);

    float w00 = (1.0f - wx) * (1.0f - wy);
    float w01 = wx * (1.0f - wy);
    float w10 = (1.0f - wx) * wy;
    float w11 = wx * wy;

    float4 fp = make_float4(0.f, 0.f, 0.f, 0.f);
    fp = f4_fma(v00, w00, fp);
    fp = f4_fma(v01, w01, fp);
    fp = f4_fma(v10, w10, fp);
    fp = f4_fma(v11, w11, fp);

    // ---- line linear (W==1 => only the y coordinate matters) ----
    float iyl = (lc.y + 1.0f) * S;
    float fl = floorf(iyl);
    float wl = iyl - fl;
    int j0 = min(max(__float2int_rn(fl), 0), DIM - 1);
    int j1 = min(j0 + 1, DIM - 1);

    const float* L = g_line_t[o];
    float4 l0 = *reinterpret_cast<const float4*>(&L[j0 * C + co]);
    float4 l1 = *reinterpret_cast<const float4*>(&L[j1 * C + co]);

    float4 flin;
    flin.x = fmaf(l1.x - l0.x, wl, l0.x);
    flin.y = fmaf(l1.y - l0.y, wl, l0.y);
    flin.z = fmaf(l1.z - l0.z, wl, l0.z);
    flin.w = fmaf(l1.w - l0.w, wl, l0.w);

    float4 r;
    r.x = fp.x * flin.x;
    r.y = fp.y * flin.y;
    r.z = fp.z * flin.z;
    r.w = fp.w * flin.w;

    reinterpret_cast<float4*>(out)[idx] = r;
}

extern "C" void kernel_launch(void* const* d_in, const int* in_sizes, int n_in,
                              void* d_out, int out_size) {
    const float* coords_plane = (const float*)d_in[0];
    const float* coords_line  = (const float*)d_in[1];
    const float* plane_xy     = (const float*)d_in[2];
    const float* plane_yz     = (const float*)d_in[3];
    const float* plane_xz     = (const float*)d_in[4];
    const float* line_x       = (const float*)d_in[5];
    const float* line_y       = (const float*)d_in[6];
    const float* line_z       = (const float*)d_in[7];
    float* out = (float*)d_out;

    {
        int total = 3 * PLANE + 3 * DIM;
        int block = 256;
        int grid = (total + block - 1) / block;
        transpose_kernel<<<grid, block>>>(plane_xy, plane_yz, plane_xz,
                                          line_x, line_y, line_z);
    }
    {
        int total = 3 * NPTS * 4;
        int block = 256;
        int grid = total / block;
        sample_kernel<<<grid, block>>>(coords_plane, coords_line, out);
    }
}